// round 5
// baseline (speedup 1.0000x reference)
#include <cuda_runtime.h>
#include <cuda_bf16.h>
#include <math.h>
#include <stdint.h>

// x: (16, 256, 64, 64, 4) f32. Per (b,c) slab = 4096 float4 = 64 KB.
// Chunked software pipeline through L2, chunk = 2 batches = 32 MB:
//   launch 0: pool(c0)                       (DRAM read, fills L2)
//   launch k: scale(c_{k-1}) + pool(c_k)     (L2 read + DRAM write | DRAM read)
//   launch 8: scale(c7)
// Scale blocks and pool blocks are interleaved by blockIdx parity so DRAM
// sees a mixed read+write stream. Excite recomputed redundantly per block.

#define NB 16
#define NC 256
#define SP 4096                  // float4 per (b,c)
#define CHUNK_B 2
#define CHUNK_BLOCKS (CHUNK_B * NC)   // 512
#define TPB 256
#define V_PER_T (SP / TPB)       // 16

__device__ float4 g_pooled[NB * NC];

// ---------------------------------------------------------------------------
__device__ __forceinline__ void do_pool(const float* __restrict__ x, int bc) {
    const float4* xp = reinterpret_cast<const float4*>(x) + (size_t)bc * SP;
    const int t = threadIdx.x;
    float4 m = make_float4(-INFINITY, -INFINITY, -INFINITY, -INFINITY);
    #pragma unroll
    for (int j = 0; j < V_PER_T; j++) {
        float4 v = xp[t + j * TPB];
        m.x = fmaxf(m.x, v.x);
        m.y = fmaxf(m.y, v.y);
        m.z = fmaxf(m.z, v.z);
        m.w = fmaxf(m.w, v.w);
    }
    #pragma unroll
    for (int o = 16; o > 0; o >>= 1) {
        m.x = fmaxf(m.x, __shfl_xor_sync(0xffffffffu, m.x, o));
        m.y = fmaxf(m.y, __shfl_xor_sync(0xffffffffu, m.y, o));
        m.z = fmaxf(m.z, __shfl_xor_sync(0xffffffffu, m.z, o));
        m.w = fmaxf(m.w, __shfl_xor_sync(0xffffffffu, m.w, o));
    }
    __shared__ float4 red[TPB / 32];
    const int lane = t & 31;
    const int warp = t >> 5;
    if (lane == 0) red[warp] = m;
    __syncthreads();
    if (t == 0) {
        float4 r = red[0];
        #pragma unroll
        for (int w = 1; w < TPB / 32; w++) {
            r.x = fmaxf(r.x, red[w].x);
            r.y = fmaxf(r.y, red[w].y);
            r.z = fmaxf(r.z, red[w].z);
            r.w = fmaxf(r.w, red[w].w);
        }
        g_pooled[bc] = r;
    }
}

// ---------------------------------------------------------------------------
__device__ __forceinline__ void do_scale(const float* __restrict__ x,
                                         const float* __restrict__ comp_w,
                                         const float* __restrict__ comp_b,
                                         const float* __restrict__ exc_w,
                                         const float* __restrict__ exc_b,
                                         float* __restrict__ out, int bc) {
    const int b = bc >> 8;
    const int c = bc & 255;
    const int t = threadIdx.x;
    const int lane = t & 31;
    const int warp = t >> 5;

    __shared__ float4 red[TPB / 32];
    __shared__ float4 u_sh;

    // Squeeze: thread t = channel t over pooled[b,:]
    float4 p = g_pooled[b * NC + t];
    float s0 = p.x * comp_w[0 * NC + t];
    float s1 = p.y * comp_w[1 * NC + t];
    float s2 = p.z * comp_w[2 * NC + t];
    float s3 = p.w * comp_w[3 * NC + t];
    #pragma unroll
    for (int o = 16; o > 0; o >>= 1) {
        s0 += __shfl_xor_sync(0xffffffffu, s0, o);
        s1 += __shfl_xor_sync(0xffffffffu, s1, o);
        s2 += __shfl_xor_sync(0xffffffffu, s2, o);
        s3 += __shfl_xor_sync(0xffffffffu, s3, o);
    }
    if (lane == 0) red[warp] = make_float4(s0, s1, s2, s3);
    __syncthreads();
    if (t == 0) {
        float r  = comp_b[0];
        float xc = comp_b[1];
        float yc = comp_b[2];
        float zc = comp_b[3];
        #pragma unroll
        for (int w = 0; w < TPB / 32; w++) {
            r  += red[w].x;
            xc += red[w].y;
            yc += red[w].z;
            zc += red[w].w;
        }
        float u1r = r + xc + yc + zc;
        float u1x = xc - r - zc + yc;
        float u1y = yc + zc - r - xc;
        float u1z = zc - yc + xc - r;
        float r2 = u1r * exc_w[0 * NC + c] + exc_b[0 * NC + c];
        float x2 = u1x * exc_w[1 * NC + c] + exc_b[1 * NC + c];
        float y2 = u1y * exc_w[2 * NC + c] + exc_b[2 * NC + c];
        float z2 = u1z * exc_w[3 * NC + c] + exc_b[3 * NC + c];
        u_sh = make_float4(r2 + x2 + y2 + z2,
                           x2 - r2 - z2 + y2,
                           y2 + z2 - r2 - x2,
                           z2 - y2 + x2 - r2);
    }
    __syncthreads();
    const float4 u = u_sh;

    const size_t base = (size_t)bc * SP;
    const float4* xp = reinterpret_cast<const float4*>(x) + base;
    float4* op = reinterpret_cast<float4*>(out) + base;
    #pragma unroll
    for (int j = 0; j < V_PER_T; j++) {
        int idx = t + j * TPB;
        float4 s = __ldcs(&xp[idx]);          // expect L2 hit, evict-first
        __stcs(&op[idx], make_float4(s.x * u.x, s.y * u.y,
                                     s.z * u.z, s.w * u.w));
    }
}

// ---------------------------------------------------------------------------
// step: scale chunk scale_b0 (if >=0) and/or pool chunk pool_b0 (if >=0).
// When both active, grid = 2*CHUNK_BLOCKS and roles interleave by parity.
// ---------------------------------------------------------------------------
__global__ void __launch_bounds__(TPB) step_kernel(const float* __restrict__ x,
                                                   const float* __restrict__ comp_w,
                                                   const float* __restrict__ comp_b,
                                                   const float* __restrict__ exc_w,
                                                   const float* __restrict__ exc_b,
                                                   float* __restrict__ out,
                                                   int scale_b0, int pool_b0) {
    if (scale_b0 >= 0 && pool_b0 >= 0) {
        int idx = blockIdx.x >> 1;
        if (blockIdx.x & 1)
            do_pool(x, pool_b0 * NC + idx);
        else
            do_scale(x, comp_w, comp_b, exc_w, exc_b, out, scale_b0 * NC + idx);
    } else if (pool_b0 >= 0) {
        do_pool(x, pool_b0 * NC + (int)blockIdx.x);
    } else {
        do_scale(x, comp_w, comp_b, exc_w, exc_b, out,
                 scale_b0 * NC + (int)blockIdx.x);
    }
}

extern "C" void kernel_launch(void* const* d_in, const int* in_sizes, int n_in,
                              void* d_out, int out_size) {
    const float* x      = (const float*)d_in[0];
    const float* comp_w = (const float*)d_in[1];
    const float* comp_b = (const float*)d_in[2];
    const float* exc_w  = (const float*)d_in[3];
    const float* exc_b  = (const float*)d_in[4];
    float* out = (float*)d_out;

    const int nchunks = NB / CHUNK_B;   // 8

    // Prologue: pool chunk 0
    step_kernel<<<CHUNK_BLOCKS, TPB>>>(x, comp_w, comp_b, exc_w, exc_b, out,
                                       -1, 0);
    // Steady state: scale(i) + pool(i+1)
    for (int i = 0; i + 1 < nchunks; i++) {
        step_kernel<<<2 * CHUNK_BLOCKS, TPB>>>(x, comp_w, comp_b, exc_w, exc_b,
                                               out, i * CHUNK_B,
                                               (i + 1) * CHUNK_B);
    }
    // Epilogue: scale last chunk
    step_kernel<<<CHUNK_BLOCKS, TPB>>>(x, comp_w, comp_b, exc_w, exc_b, out,
                                       (nchunks - 1) * CHUNK_B, -1);
}